// round 5
// baseline (speedup 1.0000x reference)
#include <cuda_runtime.h>
#include <cstdint>

#define ML   80
#define LD   10
#define BSZ  512
#define HID  32
#define ST   10
#define NKEYS 880        // ML*(ST+1)
#define GPI  171         // 3-batch groups per chain i: ceil(512/3)

__device__ uint2 g_keys[NKEYS];           // partitionable-split subkeys
__device__ float g_acc[BSZ * ML * HID];   // 5.2 MB exclusive prefix of z@W1

// ---------------- threefry2x32-20 ----------------
__device__ __forceinline__ uint32_t rotl32(uint32_t x, int r) {
    return __funnelshift_l(x, x, r);
}
__device__ __forceinline__ void threefry2x32(uint32_t k1, uint32_t k2,
                                             uint32_t &x0, uint32_t &x1) {
    uint32_t k3 = k1 ^ k2 ^ 0x1BD11BDAu;
    x0 += k1; x1 += k2;
#define R1(r) { x0 += x1; x1 = rotl32(x1, r); x1 ^= x0; }
#define RA R1(13) R1(15) R1(26) R1(6)
#define RB R1(17) R1(29) R1(16) R1(24)
    RA  x0 += k2; x1 += k3 + 1u;
    RB  x0 += k3; x1 += k1 + 2u;
    RA  x0 += k1; x1 += k2 + 3u;
    RB  x0 += k2; x1 += k3 + 4u;
    RA  x0 += k3; x1 += k1 + 5u;
#undef R1
#undef RA
#undef RB
}

__device__ __forceinline__ float bits_to_normal(uint32_t bits) {
    const float lo = __uint_as_float(0xBF7FFFFFu);       // nextafterf(-1, 0)
    float f = __fsub_rn(__uint_as_float((bits >> 9) | 0x3F800000u), 1.0f);
    float span = __fsub_rn(1.0f, lo);                    // == 2.0f
    float u = __fadd_rn(__fmul_rn(f, span), lo);
    u = fmaxf(u, lo);
    return __fmul_rn(1.41421356237309515f, erfinvf(u));
}

__device__ __forceinline__ float draw_normal(uint2 key, uint32_t m) {
    uint32_t x0 = 0u, x1 = m;
    threefry2x32(key.x, key.y, x0, x1);
    return bits_to_normal(x0 ^ x1);
}

// ---- k_init: blocks [0,256) prefix-scan (2 batches each), [256,260) key table ----
__global__ void __launch_bounds__(256) k_init(const float* __restrict__ z_mean,
                                              const float* __restrict__ W1) {
    int tid = threadIdx.x;

    if (blockIdx.x >= 256) {
        int j = (blockIdx.x - 256) * 256 + tid;
        if (j < NKEYS) {
            uint32_t x0 = 0u, x1 = (uint32_t)j;   // partitionable split of key(1337)
            threefry2x32(0u, 1337u, x0, x1);
            g_keys[j] = make_uint2(x0, x1);
        }
        return;
    }

    // ===== prefix-scan: one block per 2 batches =====
    __shared__ float zb[2 * ML * LD];          // 1600
    __shared__ float sp[2][ML * HID];          // 2 x 2560
    int b0 = blockIdx.x * 2;

    for (int p = tid; p < 2 * ML * LD; p += 256)
        zb[p] = z_mean[b0 * ML * LD + p];
    __syncthreads();

    // P[l][j] for both batches; W1 element loaded once, used twice
#pragma unroll
    for (int r = 0; r < 10; r++) {
        int p = tid + 256 * r;               // 2560 positions
        int l = p >> 5, j = p & 31;
        float a0 = 0.f, a1 = 0.f;
#pragma unroll
        for (int d = 0; d < LD; d++) {
            float w = W1[(l * LD + d) * HID + j];
            a0 = fmaf(zb[l * LD + d],           w, a0);
            a1 = fmaf(zb[ML * LD + l * LD + d], w, a1);
        }
        sp[0][p] = a0;
        sp[1][p] = a1;
    }
    __syncthreads();

    // Hillis-Steele inclusive scan over l for both batches
#pragma unroll
    for (int off = 1; off < ML; off <<= 1) {
        float v0[10], v1[10];
#pragma unroll
        for (int r = 0; r < 10; r++) {
            int p = tid + 256 * r;
            int l = p >> 5;
            float add0 = (l >= off) ? sp[0][p - off * HID] : 0.f;
            float add1 = (l >= off) ? sp[1][p - off * HID] : 0.f;
            v0[r] = sp[0][p] + add0;
            v1[r] = sp[1][p] + add1;
        }
        __syncthreads();
#pragma unroll
        for (int r = 0; r < 10; r++) {
            sp[0][tid + 256 * r] = v0[r];
            sp[1][tid + 256 * r] = v1[r];
        }
        __syncthreads();
    }

#pragma unroll
    for (int r = 0; r < 10; r++) {
        int p = tid + 256 * r;
        int l = p >> 5;
        g_acc[(b0 + 0) * ML * HID + p] = (l == 0) ? 0.f : sp[0][p - HID];
        g_acc[(b0 + 1) * ML * HID + p] = (l == 0) ? 0.f : sp[1][p - HID];
    }
}

// ---------------- k_main: fused noise + sim, one warp per (i, 3-batch group) ----------------
__global__ void __launch_bounds__(128, 5) k_main(
    const float* __restrict__ z_mean, const float* __restrict__ z_log_var,
    const float* __restrict__ W1, const float* __restrict__ b1,
    const float* __restrict__ W2, const float* __restrict__ b2,
    float* __restrict__ out)
{
    __shared__ __align__(16) float s_xt[4][3][12];   // stride 12 (16B-aligned bases)
    __shared__ __align__(16) float s_rh[4][3][36];   // stride 36 (conflict-free f4)
    __shared__ __align__(16) float s_w2[LD][36];     // W2 transposed, padded

    int tid = threadIdx.x;
    int w = tid >> 5;
    int lane = tid & 31;

    // block-shared W2 transpose: s_w2[d][j] = W2[j*10+d]
    for (int p = tid; p < HID * LD; p += 128)
        s_w2[p % LD][p / LD] = W2[p];
    __syncthreads();

    int gw = blockIdx.x * 4 + w;       // 13680 warps exactly (80*171)
    int i = gw / GPI;
    int g = gw - i * GPI;
    int bs = 3 * g;

    // ---- (k,d)-role indices ----
    int kk = lane / LD;                      // 0..3 (lanes 30,31 -> 3)
    int d  = lane - kk * LD;
    int kc = min(kk, 2);
    bool kval = (kk < 3) && (bs + kk < BSZ);
    int bk2 = min(bs + kc, BSZ - 1);
    int zi = (bk2 * ML + i) * LD + d;
    uint32_t m = (uint32_t)(bk2 * LD + d);
    const uint2* kp = g_keys + i * 11;

    // ---- j-role constants (lane = hidden unit j) ----
    float w1i[LD];
#pragma unroll
    for (int dd = 0; dd < LD; dd++) w1i[dd] = W1[(i * LD + dd) * HID + lane];
    float w1t = W1[800 * HID + lane];
    float b1v = b1[lane];
    float accb[3];
#pragma unroll
    for (int k = 0; k < 3; k++) {
        int bk = min(bs + k, BSZ - 1);
        accb[k] = g_acc[(bk * ML + i) * HID + lane] + b1v;
    }

    // ---- (k,d)-role constants ----
    float mu   = z_mean[zi];
    float sig  = expf(z_log_var[zi]);
    float sstd = sqrtf(sig);
    float b2v  = b2[d];

    float xt  = mu + sstd * draw_normal(kp[0], m);
    float err = 0.f;
    float halfsig = 0.5f * sig;
    float ssdt = sstd * 0.31622776601683794f;   // sstd * sqrt(DT)
    float rstd = 1.0f / sstd;

    if (lane < 3 * LD) s_xt[w][kk][d] = xt;
    __syncwarp();

#pragma unroll
    for (int s = 0; s < ST; s++) {
        // start next noise draw early; its dep-chain hides under the fma work
        float nv = draw_normal(kp[s + 1], m);

        float t = (float)i + (float)s * 0.1f;
        // h-phase: lane = j, 3 tasks, vectorized uniform s_xt reads
#pragma unroll
        for (int k = 0; k < 3; k++) {
            float4 xa = *(const float4*)&s_xt[w][k][0];
            float4 xb = *(const float4*)&s_xt[w][k][4];
            float2 xc = *(const float2*)&s_xt[w][k][8];
            float h0 = fmaf(t, w1t, accb[k]);
            float h1 = 0.f;
            h0 = fmaf(xa.x, w1i[0], h0);  h1 = fmaf(xa.y, w1i[1], h1);
            h0 = fmaf(xa.z, w1i[2], h0);  h1 = fmaf(xa.w, w1i[3], h1);
            h0 = fmaf(xb.x, w1i[4], h0);  h1 = fmaf(xb.y, w1i[5], h1);
            h0 = fmaf(xb.z, w1i[6], h0);  h1 = fmaf(xb.w, w1i[7], h1);
            h0 = fmaf(xc.x, w1i[8], h0);  h1 = fmaf(xc.y, w1i[9], h1);
            s_rh[w][k][lane] = fmaxf(h0 + h1, 0.f);
        }
        __syncwarp();
        // sc-phase: lane = (k,d); W2 column from shared, 4 accumulators
        const float4* rp = (const float4*)s_rh[w][kc];
        const float4* wp = (const float4*)s_w2[d];
        float sc0 = b2v, sc1 = 0.f, sc2 = 0.f, sc3 = 0.f;
#pragma unroll
        for (int q = 0; q < 8; q++) {
            float4 v = rp[q];
            float4 c = wp[q];
            sc0 = fmaf(v.x, c.x, sc0);
            sc1 = fmaf(v.y, c.y, sc1);
            sc2 = fmaf(v.z, c.z, sc2);
            sc3 = fmaf(v.w, c.w, sc3);
        }
        float sc = (sc0 + sc1) + (sc2 + sc3);
        err += fabsf((mu - xt) * rstd - sc);
        xt = fmaf(halfsig, sc, xt) + ssdt * nv;
        if (lane < 3 * LD) s_xt[w][kk][d] = xt;
        __syncwarp();
    }

    if (kval) {
        out[zi] = xt;                         // sequence
        out[BSZ * ML * LD + zi] = err;        // score_error
    }
}

// ---------------- launch ----------------
extern "C" void kernel_launch(void* const* d_in, const int* in_sizes, int n_in,
                              void* d_out, int out_size) {
    const float* z_mean    = (const float*)d_in[0];
    const float* z_log_var = (const float*)d_in[1];
    const float* W1        = (const float*)d_in[2];
    const float* b1        = (const float*)d_in[3];
    const float* W2        = (const float*)d_in[4];
    const float* b2        = (const float*)d_in[5];
    float* out = (float*)d_out;

    k_init<<<260, 256>>>(z_mean, W1);                                          // 256 scan + 4 key blocks
    k_main<<<(ML * GPI) / 4, 128>>>(z_mean, z_log_var, W1, b1, W2, b2, out);   // 3420 blocks
}

// round 6
// speedup vs baseline: 1.2177x; 1.2177x over previous
#include <cuda_runtime.h>
#include <cstdint>

#define ML   80
#define LD   10
#define BSZ  512
#define HID  32
#define ST   10
#define NKEYS 880        // ML*(ST+1)
#define GPI  171         // 3-batch groups per chain i: ceil(512/3)

__device__ uint2 g_keys[NKEYS];           // partitionable-split subkeys
__device__ float g_acc[BSZ * ML * HID];   // 5.2 MB exclusive prefix of z@W1

// ---------------- f32x2 packed helpers (PTX-only on Blackwell) ----------------
__device__ __forceinline__ unsigned long long pk2(float lo, float hi) {
    unsigned long long r;
    asm("mov.b64 %0, {%1, %2};" : "=l"(r) : "f"(lo), "f"(hi));
    return r;
}
__device__ __forceinline__ void upk2(unsigned long long v, float &lo, float &hi) {
    asm("mov.b64 {%0, %1}, %2;" : "=f"(lo), "=f"(hi) : "l"(v));
}
__device__ __forceinline__ unsigned long long fma2(unsigned long long a,
                                                   unsigned long long b,
                                                   unsigned long long c) {
    unsigned long long d;
    asm("fma.rn.f32x2 %0, %1, %2, %3;" : "=l"(d) : "l"(a), "l"(b), "l"(c));
    return d;
}

// ---------------- threefry2x32-20 ----------------
__device__ __forceinline__ uint32_t rotl32(uint32_t x, int r) {
    return __funnelshift_l(x, x, r);
}
__device__ __forceinline__ void threefry2x32(uint32_t k1, uint32_t k2,
                                             uint32_t &x0, uint32_t &x1) {
    uint32_t k3 = k1 ^ k2 ^ 0x1BD11BDAu;
    x0 += k1; x1 += k2;
#define R1(r) { x0 += x1; x1 = rotl32(x1, r); x1 ^= x0; }
#define RA R1(13) R1(15) R1(26) R1(6)
#define RB R1(17) R1(29) R1(16) R1(24)
    RA  x0 += k2; x1 += k3 + 1u;
    RB  x0 += k3; x1 += k1 + 2u;
    RA  x0 += k1; x1 += k2 + 3u;
    RB  x0 += k2; x1 += k3 + 4u;
    RA  x0 += k3; x1 += k1 + 5u;
#undef R1
#undef RA
#undef RB
}

__device__ __forceinline__ float bits_to_normal(uint32_t bits) {
    const float lo = __uint_as_float(0xBF7FFFFFu);       // nextafterf(-1, 0)
    float f = __fsub_rn(__uint_as_float((bits >> 9) | 0x3F800000u), 1.0f);
    float span = __fsub_rn(1.0f, lo);                    // == 2.0f
    float u = __fadd_rn(__fmul_rn(f, span), lo);
    u = fmaxf(u, lo);
    return __fmul_rn(1.41421356237309515f, erfinvf(u));
}

__device__ __forceinline__ float draw_normal(uint2 key, uint32_t m) {
    uint32_t x0 = 0u, x1 = m;
    threefry2x32(key.x, key.y, x0, x1);
    return bits_to_normal(x0 ^ x1);
}

// ---- k_init: blocks [0,256) prefix-scan (2 batches each), [256,260) key table ----
__global__ void __launch_bounds__(256) k_init(const float* __restrict__ z_mean,
                                              const float* __restrict__ W1) {
    int tid = threadIdx.x;

    if (blockIdx.x >= 256) {
        int j = (blockIdx.x - 256) * 256 + tid;
        if (j < NKEYS) {
            uint32_t x0 = 0u, x1 = (uint32_t)j;   // partitionable split of key(1337)
            threefry2x32(0u, 1337u, x0, x1);
            g_keys[j] = make_uint2(x0, x1);
        }
        return;
    }

    __shared__ float zb[2 * ML * LD];
    __shared__ float sp[2][ML * HID];
    int b0 = blockIdx.x * 2;

    for (int p = tid; p < 2 * ML * LD; p += 256)
        zb[p] = z_mean[b0 * ML * LD + p];
    __syncthreads();

#pragma unroll
    for (int r = 0; r < 10; r++) {
        int p = tid + 256 * r;
        int l = p >> 5, j = p & 31;
        float a0 = 0.f, a1 = 0.f;
#pragma unroll
        for (int d = 0; d < LD; d++) {
            float w = W1[(l * LD + d) * HID + j];
            a0 = fmaf(zb[l * LD + d],           w, a0);
            a1 = fmaf(zb[ML * LD + l * LD + d], w, a1);
        }
        sp[0][p] = a0;
        sp[1][p] = a1;
    }
    __syncthreads();

#pragma unroll
    for (int off = 1; off < ML; off <<= 1) {
        float v0[10], v1[10];
#pragma unroll
        for (int r = 0; r < 10; r++) {
            int p = tid + 256 * r;
            int l = p >> 5;
            v0[r] = sp[0][p] + ((l >= off) ? sp[0][p - off * HID] : 0.f);
            v1[r] = sp[1][p] + ((l >= off) ? sp[1][p - off * HID] : 0.f);
        }
        __syncthreads();
#pragma unroll
        for (int r = 0; r < 10; r++) {
            sp[0][tid + 256 * r] = v0[r];
            sp[1][tid + 256 * r] = v1[r];
        }
        __syncthreads();
    }

#pragma unroll
    for (int r = 0; r < 10; r++) {
        int p = tid + 256 * r;
        int l = p >> 5;
        g_acc[(b0 + 0) * ML * HID + p] = (l == 0) ? 0.f : sp[0][p - HID];
        g_acc[(b0 + 1) * ML * HID + p] = (l == 0) ? 0.f : sp[1][p - HID];
    }
}

// ---------------- k_main: fused noise + sim, f32x2 math, one warp per (i, 3-batch) ----------------
__global__ void __launch_bounds__(128, 5) k_main(
    const float* __restrict__ z_mean, const float* __restrict__ z_log_var,
    const float* __restrict__ W1, const float* __restrict__ b1,
    const float* __restrict__ W2, const float* __restrict__ b2,
    float* __restrict__ out)
{
    __shared__ __align__(16) float s_xtp[4][LD][2];   // (task0, task1) interleaved
    __shared__ __align__(16) float s_xt2[4][LD][2];   // (task2, task2) duplicated
    __shared__ __align__(16) float s_rh[4][3][36];    // padded rows: conflict-free

    int tid = threadIdx.x;
    int w = tid >> 5;
    int lane = tid & 31;

    int gw = blockIdx.x * 4 + w;       // 13680 warps exactly (80*171)
    int i = gw / GPI;
    int g = gw - i * GPI;
    int bs = 3 * g;

    // ---- (k,d)-role indices ----
    int kk = lane / LD;                      // 0..3 (lanes 30,31 -> 3)
    int d  = lane - kk * LD;
    int kc = min(kk, 2);
    bool kval = (kk < 3) && (bs + kk < BSZ);
    int bk2 = min(bs + kc, BSZ - 1);
    int zi = (bk2 * ML + i) * LD + d;
    uint32_t m = (uint32_t)(bk2 * LD + d);
    const uint2* kp = g_keys + i * 11;

    // ---- j-role constants (lane = hidden unit j), packed ----
    unsigned long long w1p[LD];
#pragma unroll
    for (int dd = 0; dd < LD; dd++) {
        float v = W1[(i * LD + dd) * HID + lane];
        w1p[dd] = pk2(v, v);
    }
    float w1t = W1[800 * HID + lane];
    unsigned long long w1tp = pk2(w1t, w1t);
    float b1v = b1[lane];
    float a0 = g_acc[(min(bs + 0, BSZ - 1) * ML + i) * HID + lane] + b1v;
    float a1 = g_acc[(min(bs + 1, BSZ - 1) * ML + i) * HID + lane] + b1v;
    float a2 = g_acc[(min(bs + 2, BSZ - 1) * ML + i) * HID + lane] + b1v;
    unsigned long long acc01 = pk2(a0, a1);
    unsigned long long acc23 = pk2(a2, a2);

    // ---- (k,d)-role constants, W2 column packed in register pairs ----
    float mu   = z_mean[zi];
    float sig  = expf(z_log_var[zi]);
    float sstd = sqrtf(sig);
    float b2v  = b2[d];
    unsigned long long w2p[16];
#pragma unroll
    for (int p = 0; p < 16; p++)
        w2p[p] = pk2(W2[(2 * p) * LD + d], W2[(2 * p + 1) * LD + d]);

    float xt  = mu + sstd * draw_normal(kp[0], m);
    float err = 0.f;
    float halfsig = 0.5f * sig;
    float ssdt = sstd * 0.31622776601683794f;   // sstd * sqrt(DT)
    float rstd = 1.0f / sstd;

    if (kk < 2)       s_xtp[w][d][kk] = xt;
    else if (kk == 2) *(unsigned long long*)&s_xt2[w][d][0] = pk2(xt, xt);
    __syncwarp();

#pragma unroll
    for (int s = 0; s < ST; s++) {
        // independent alu-pipe work: next noise draw overlaps the fma chains
        float nv = draw_normal(kp[s + 1], m);

        float t = (float)i + (float)s * 0.1f;
        unsigned long long tp = pk2(t, t);
        // h-phase: lane = j; two packed 11-deep chains cover 3 tasks
        unsigned long long h01 = fma2(tp, w1tp, acc01);
        unsigned long long h23 = fma2(tp, w1tp, acc23);
#pragma unroll
        for (int dd = 0; dd < LD; dd++) {
            unsigned long long x01 = *(const unsigned long long*)&s_xtp[w][dd][0];
            unsigned long long x23 = *(const unsigned long long*)&s_xt2[w][dd][0];
            h01 = fma2(x01, w1p[dd], h01);
            h23 = fma2(x23, w1p[dd], h23);
        }
        float h0, h1, h2, hx;
        upk2(h01, h0, h1);
        upk2(h23, h2, hx);
        s_rh[w][0][lane] = fmaxf(h0, 0.f);
        s_rh[w][1][lane] = fmaxf(h1, 0.f);
        s_rh[w][2][lane] = fmaxf(h2, 0.f);
        __syncwarp();

        // sc-phase: lane = (k,d); LDS.128 = two f32x2 operands, zero pack cost
        const ulonglong2* rp = (const ulonglong2*)s_rh[w][kc];
        unsigned long long sA = pk2(b2v, 0.f);
        unsigned long long sB = pk2(0.f, 0.f);
#pragma unroll
        for (int q = 0; q < 8; q++) {
            ulonglong2 rv = rp[q];
            sA = fma2(rv.x, w2p[2 * q],     sA);
            sB = fma2(rv.y, w2p[2 * q + 1], sB);
        }
        float p0, p1, p2, p3;
        upk2(sA, p0, p1);
        upk2(sB, p2, p3);
        float sc = (p0 + p1) + (p2 + p3);

        err += fabsf((mu - xt) * rstd - sc);
        xt = fmaf(halfsig, sc, xt) + ssdt * nv;
        if (kk < 2)       s_xtp[w][d][kk] = xt;
        else if (kk == 2) *(unsigned long long*)&s_xt2[w][d][0] = pk2(xt, xt);
        __syncwarp();
    }

    if (kval) {
        out[zi] = xt;                         // sequence
        out[BSZ * ML * LD + zi] = err;        // score_error
    }
}

// ---------------- launch ----------------
extern "C" void kernel_launch(void* const* d_in, const int* in_sizes, int n_in,
                              void* d_out, int out_size) {
    const float* z_mean    = (const float*)d_in[0];
    const float* z_log_var = (const float*)d_in[1];
    const float* W1        = (const float*)d_in[2];
    const float* b1        = (const float*)d_in[3];
    const float* W2        = (const float*)d_in[4];
    const float* b2        = (const float*)d_in[5];
    float* out = (float*)d_out;

    k_init<<<260, 256>>>(z_mean, W1);                                          // 256 scan + 4 key blocks
    k_main<<<(ML * GPI) / 4, 128>>>(z_mean, z_log_var, W1, b1, W2, b2, out);   // 3420 blocks
}